// round 2
// baseline (speedup 1.0000x reference)
#include <cuda_runtime.h>

// RelationalGraphConvLayer: out[b,i,d] = bias[d] + sum_r rinv[b,r,i] * sum_j adj[b,r,i,j] * (text[b] @ W[r])[j,d]
// Shapes: text[8,1024,256], adj[8,4,1024,1024], weight[4,256,256], bias[256] -> out[8,1024,256], all fp32.

#define B_    8
#define R_    4
#define N_    1024
#define DIN_  256
#define DOUT_ 256

// Scratch (device globals: allocation inside kernel_launch is forbidden)
__device__ float g_Z[(size_t)B_ * R_ * N_ * DOUT_];   // Z[b,r,j,d] = text[b] @ W[r]   (33.5 MB)
__device__ float g_rinv[B_ * R_ * N_];                // 1/rowsum (0 if rowsum==0)

// ---------------------------------------------------------------------------
// Rowsum: one warp per adjacency row (1024 floats), warp-reduce, write 1/sum.
// ---------------------------------------------------------------------------
__global__ void rowsum_kernel(const float* __restrict__ adj) {
    int row  = blockIdx.x * blockDim.y + threadIdx.y;   // 0 .. B*R*N-1
    int lane = threadIdx.x;
    const float* p = adj + (size_t)row * N_;
    float s = 0.f;
#pragma unroll
    for (int t = 0; t < N_ / 128; ++t) {
        float4 v = *reinterpret_cast<const float4*>(p + t * 128 + lane * 4);
        s += (v.x + v.y) + (v.z + v.w);
    }
#pragma unroll
    for (int o = 16; o > 0; o >>= 1) s += __shfl_xor_sync(0xffffffffu, s, o);
    if (lane == 0) g_rinv[row] = (s == 0.f) ? 0.f : 1.0f / s;
}

// ---------------------------------------------------------------------------
// Classic SGEMM tiling: BM=BN=128, BK=8, 256 threads, 8x8 per-thread microtile.
// ---------------------------------------------------------------------------
#define BM 128
#define BN 128
#define BK 8
#define TM 8
#define TN 8

// Stage 1: Z[b,r] = text[b] (1024x256) @ W[r] (256x256)
__global__ __launch_bounds__(256) void gemm_textw(const float* __restrict__ text,
                                                  const float* __restrict__ weight) {
    const int bz = blockIdx.z;            // b*R + r
    const int b  = bz >> 2;
    const int r  = bz & 3;
    const float* A  = text   + (size_t)b * N_ * DIN_;
    const float* Bw = weight + (size_t)r * DIN_ * DOUT_;
    float*       C  = g_Z    + (size_t)bz * N_ * DOUT_;

    const int tile_m = blockIdx.y * BM;
    const int tile_n = blockIdx.x * BN;

    __shared__ float As[BK][BM];
    __shared__ float Bs[BK][BN];

    const int tid = threadIdx.x;
    const int tr  = tid >> 4;             // 0..15
    const int tc  = tid & 15;             // 0..15

    const int aRow = tid >> 1;            // 0..127
    const int aCol = (tid & 1) * 4;       // 0 or 4
    const int bRow = tid >> 5;            // 0..7
    const int bCol = (tid & 31) * 4;      // 0..124

    float acc[TM][TN];
#pragma unroll
    for (int m = 0; m < TM; ++m)
#pragma unroll
        for (int n = 0; n < TN; ++n) acc[m][n] = 0.f;

    for (int k0 = 0; k0 < DIN_; k0 += BK) {
        float4 av = *reinterpret_cast<const float4*>(A + (size_t)(tile_m + aRow) * DIN_ + k0 + aCol);
        As[aCol + 0][aRow] = av.x;
        As[aCol + 1][aRow] = av.y;
        As[aCol + 2][aRow] = av.z;
        As[aCol + 3][aRow] = av.w;
        *reinterpret_cast<float4*>(&Bs[bRow][bCol]) =
            *reinterpret_cast<const float4*>(Bw + (size_t)(k0 + bRow) * DOUT_ + tile_n + bCol);
        __syncthreads();
#pragma unroll
        for (int k = 0; k < BK; ++k) {
            float af[TM], bf[TN];
#pragma unroll
            for (int m = 0; m < TM; ++m) af[m] = As[k][tr * TM + m];
#pragma unroll
            for (int n = 0; n < TN; ++n) bf[n] = Bs[k][tc * TN + n];
#pragma unroll
            for (int m = 0; m < TM; ++m)
#pragma unroll
                for (int n = 0; n < TN; ++n) acc[m][n] += af[m] * bf[n];
        }
        __syncthreads();
    }

#pragma unroll
    for (int m = 0; m < TM; ++m) {
        float* crow = C + (size_t)(tile_m + tr * TM + m) * DOUT_ + tile_n + tc * TN;
#pragma unroll
        for (int n = 0; n < TN; n += 4) {
            float4 v = make_float4(acc[m][n], acc[m][n + 1], acc[m][n + 2], acc[m][n + 3]);
            *reinterpret_cast<float4*>(crow + n) = v;
        }
    }
}

// Stage 2: out[b] = bias + sum_r diag(rinv[b,r]) * adj[b,r] (1024x1024) @ Z[b,r] (1024x256)
// rinv folded into the A-tile load (row scale), single accumulator across r.
__global__ __launch_bounds__(256) void gemm_adjz(const float* __restrict__ adj,
                                                 const float* __restrict__ bias,
                                                 float* __restrict__ out) {
    const int b = blockIdx.z;
    const int tile_m = blockIdx.y * BM;
    const int tile_n = blockIdx.x * BN;

    __shared__ float As[BK][BM];
    __shared__ float Bs[BK][BN];

    const int tid = threadIdx.x;
    const int tr  = tid >> 4;
    const int tc  = tid & 15;

    const int aRow = tid >> 1;
    const int aCol = (tid & 1) * 4;
    const int bRow = tid >> 5;
    const int bCol = (tid & 31) * 4;

    float acc[TM][TN];
#pragma unroll
    for (int m = 0; m < TM; ++m)
#pragma unroll
        for (int n = 0; n < TN; ++n) acc[m][n] = 0.f;

    for (int r = 0; r < R_; ++r) {
        const int brn = (b * R_ + r);
        const float* A  = adj  + (size_t)brn * N_ * N_;
        const float* Bz = g_Z  + (size_t)brn * N_ * DOUT_;
        const float  rv = g_rinv[brn * N_ + tile_m + aRow];   // scale for my loaded row

        for (int k0 = 0; k0 < N_; k0 += BK) {
            float4 av = *reinterpret_cast<const float4*>(A + (size_t)(tile_m + aRow) * N_ + k0 + aCol);
            As[aCol + 0][aRow] = av.x * rv;
            As[aCol + 1][aRow] = av.y * rv;
            As[aCol + 2][aRow] = av.z * rv;
            As[aCol + 3][aRow] = av.w * rv;
            *reinterpret_cast<float4*>(&Bs[bRow][bCol]) =
                *reinterpret_cast<const float4*>(Bz + (size_t)(k0 + bRow) * DOUT_ + tile_n + bCol);
            __syncthreads();
#pragma unroll
            for (int k = 0; k < BK; ++k) {
                float af[TM], bf[TN];
#pragma unroll
                for (int m = 0; m < TM; ++m) af[m] = As[k][tr * TM + m];
#pragma unroll
                for (int n = 0; n < TN; ++n) bf[n] = Bs[k][tc * TN + n];
#pragma unroll
                for (int m = 0; m < TM; ++m)
#pragma unroll
                    for (int n = 0; n < TN; ++n) acc[m][n] += af[m] * bf[n];
            }
            __syncthreads();
        }
    }

    float bi[TN];
#pragma unroll
    for (int n = 0; n < TN; ++n) bi[n] = bias[tile_n + tc * TN + n];

#pragma unroll
    for (int m = 0; m < TM; ++m) {
        float* crow = out + (size_t)b * N_ * DOUT_ + (size_t)(tile_m + tr * TM + m) * DOUT_ + tile_n + tc * TN;
#pragma unroll
        for (int n = 0; n < TN; n += 4) {
            float4 v = make_float4(acc[m][n] + bi[n], acc[m][n + 1] + bi[n + 1],
                                   acc[m][n + 2] + bi[n + 2], acc[m][n + 3] + bi[n + 3]);
            *reinterpret_cast<float4*>(crow + n) = v;
        }
    }
}

// ---------------------------------------------------------------------------
extern "C" void kernel_launch(void* const* d_in, const int* in_sizes, int n_in,
                              void* d_out, int out_size) {
    const float* text   = (const float*)d_in[0];  // [8,1024,256]
    const float* adj    = (const float*)d_in[1];  // [8,4,1024,1024]
    const float* weight = (const float*)d_in[2];  // [4,256,256]
    const float* bias   = (const float*)d_in[3];  // [256]
    float* out = (float*)d_out;                   // [8,1024,256]

    // 1) rinv = 1/rowsum(adj)
    {
        dim3 blk(32, 8);
        dim3 grd((B_ * R_ * N_) / 8);
        rowsum_kernel<<<grd, blk>>>(adj);
    }
    // 2) Z[b,r] = text[b] @ W[r]
    {
        dim3 blk(256);
        dim3 grd(DOUT_ / BN, N_ / BM, B_ * R_);   // (2, 8, 32)
        gemm_textw<<<grd, blk>>>(text, weight);
    }
    // 3) out[b] = bias + sum_r diag(rinv) adj[b,r] @ Z[b,r]
    {
        dim3 blk(256);
        dim3 grd(DOUT_ / BN, N_ / BM, B_);        // (2, 8, 8)
        gemm_adjz<<<grd, blk>>>(adj, bias, out);
    }
}

// round 5
// speedup vs baseline: 3.2612x; 3.2612x over previous
#include <cuda_runtime.h>
#include <cuda_bf16.h>
#include <cstdint>

#define B_    8
#define R_    4
#define N_    1024
#define DIN_  256
#define DOUT_ 256

// ---------------------------------------------------------------------------
// Global scratch (device globals; allocation in kernel_launch is forbidden)
// ---------------------------------------------------------------------------
__device__ __nv_bfloat16 g_text_hi[(size_t)B_ * N_ * DIN_];
__device__ __nv_bfloat16 g_text_lo[(size_t)B_ * N_ * DIN_];
__device__ __nv_bfloat16 g_W_hi[(size_t)R_ * DIN_ * DOUT_];
__device__ __nv_bfloat16 g_W_lo[(size_t)R_ * DIN_ * DOUT_];
__device__ __nv_bfloat16 g_Z_hi[(size_t)B_ * R_ * N_ * DOUT_];   // Z[b,r][j][d]
__device__ __nv_bfloat16 g_Z_lo[(size_t)B_ * R_ * N_ * DOUT_];
__device__ float         g_rinv[B_ * R_ * N_];

// ---------------------------------------------------------------------------
// PTX helpers (compute_103-safe: mma.sync / ldmatrix / cp.async, all sm_80+)
// ---------------------------------------------------------------------------
__device__ __forceinline__ uint32_t smem_u32(const void* p) {
    uint32_t a;
    asm("{ .reg .u64 t; cvta.to.shared.u64 t, %1; cvt.u32.u64 %0, t; }" : "=r"(a) : "l"(p));
    return a;
}
__device__ __forceinline__ void ldsm_x4(uint32_t addr, uint32_t& r0, uint32_t& r1,
                                        uint32_t& r2, uint32_t& r3) {
    asm volatile("ldmatrix.sync.aligned.m8n8.x4.shared.b16 {%0,%1,%2,%3}, [%4];"
                 : "=r"(r0), "=r"(r1), "=r"(r2), "=r"(r3) : "r"(addr));
}
__device__ __forceinline__ void ldsm_x4_t(uint32_t addr, uint32_t& r0, uint32_t& r1,
                                          uint32_t& r2, uint32_t& r3) {
    asm volatile("ldmatrix.sync.aligned.m8n8.x4.trans.shared.b16 {%0,%1,%2,%3}, [%4];"
                 : "=r"(r0), "=r"(r1), "=r"(r2), "=r"(r3) : "r"(addr));
}
__device__ __forceinline__ void mma_bf16(float* c, const uint32_t a[4], uint32_t b0, uint32_t b1) {
    asm volatile("mma.sync.aligned.m16n8k16.row.col.f32.bf16.bf16.f32 "
                 "{%0,%1,%2,%3}, {%4,%5,%6,%7}, {%8,%9}, {%0,%1,%2,%3};"
                 : "+f"(c[0]), "+f"(c[1]), "+f"(c[2]), "+f"(c[3])
                 : "r"(a[0]), "r"(a[1]), "r"(a[2]), "r"(a[3]), "r"(b0), "r"(b1));
}
#define CP_ASYNC16(dst, src) \
    asm volatile("cp.async.cg.shared.global [%0], [%1], 16;" :: "r"(dst), "l"(src) : "memory")
#define CP_COMMIT()  asm volatile("cp.async.commit_group;" ::: "memory")
#define CP_WAIT0()   asm volatile("cp.async.wait_group 0;" ::: "memory")

__device__ __forceinline__ void split_pack2(float x, float y, uint32_t& hw, uint32_t& lw) {
    __nv_bfloat16 hx = __float2bfloat16(x), hy = __float2bfloat16(y);
    __nv_bfloat16 lx = __float2bfloat16(x - __bfloat162float(hx));
    __nv_bfloat16 ly = __float2bfloat16(y - __bfloat162float(hy));
    hw = ((uint32_t)__bfloat16_as_ushort(hy) << 16) | __bfloat16_as_ushort(hx);
    lw = ((uint32_t)__bfloat16_as_ushort(ly) << 16) | __bfloat16_as_ushort(lx);
}

// ---------------------------------------------------------------------------
// smem layout (per pipeline buffer), padded strides — conflict-free ldmatrix
//   A: 128 rows x 64 bf16, stride 144B      (18432 B per array)
//   B:  64 rows x 128 bf16, stride 272B     (17408 B per array)
// ---------------------------------------------------------------------------
#define A_STRIDE  144
#define B_STRIDE  272
#define OFF_AHI   0
#define OFF_ALO   18432
#define OFF_BHI   36864
#define OFF_BLO   54272
#define BUF_BYTES 71680
#define SMEM_TOTAL (2 * BUF_BYTES)   // 143360

// Warp-tile MMA over one K=64 chunk: warp (wm,wn) computes 32x64 of the 128x128 tile.
// 3 passes: ah*bh + ah*bl + al*bh (split-bf16 ~fp32 accuracy).
__device__ __forceinline__ void compute_chunk(uint32_t sb_buf, int wm, int wn, int g, int lr,
                                              float (&acc)[2][8][4]) {
#pragma unroll
    for (int ks = 0; ks < 4; ++ks) {
        const int k0 = ks * 16;
        uint32_t ah[2][4], al[2][4];
#pragma unroll
        for (int mf = 0; mf < 2; ++mf) {
            uint32_t row  = wm * 32 + mf * 16 + (g & 1) * 8 + lr;
            uint32_t colb = (uint32_t)((g >> 1) * 16 + k0 * 2);
            ldsm_x4(sb_buf + OFF_AHI + row * A_STRIDE + colb,
                    ah[mf][0], ah[mf][1], ah[mf][2], ah[mf][3]);
            ldsm_x4(sb_buf + OFF_ALO + row * A_STRIDE + colb,
                    al[mf][0], al[mf][1], al[mf][2], al[mf][3]);
        }
        uint32_t bh[8][2], bl[8][2];
#pragma unroll
        for (int nb = 0; nb < 4; ++nb) {
            uint32_t krow = (uint32_t)(k0 + (g & 1) * 8 + lr);
            uint32_t colb = (uint32_t)((wn * 64 + nb * 16 + (g >> 1) * 8) * 2);
            uint32_t q0, q1, q2, q3;
            ldsm_x4_t(sb_buf + OFF_BHI + krow * B_STRIDE + colb, q0, q1, q2, q3);
            bh[nb * 2][0] = q0; bh[nb * 2][1] = q1;
            bh[nb * 2 + 1][0] = q2; bh[nb * 2 + 1][1] = q3;
            ldsm_x4_t(sb_buf + OFF_BLO + krow * B_STRIDE + colb, q0, q1, q2, q3);
            bl[nb * 2][0] = q0; bl[nb * 2][1] = q1;
            bl[nb * 2 + 1][0] = q2; bl[nb * 2 + 1][1] = q3;
        }
#pragma unroll
        for (int mf = 0; mf < 2; ++mf)
#pragma unroll
            for (int nf = 0; nf < 8; ++nf) {
                mma_bf16(acc[mf][nf], ah[mf], bh[nf][0], bh[nf][1]);
                mma_bf16(acc[mf][nf], ah[mf], bl[nf][0], bl[nf][1]);
                mma_bf16(acc[mf][nf], al[mf], bh[nf][0], bh[nf][1]);
            }
    }
}

// ---------------------------------------------------------------------------
// conv_inputs: split text & W into bf16 hi/lo arrays.
// ---------------------------------------------------------------------------
__global__ __launch_bounds__(256) void conv_inputs(const float* __restrict__ text,
                                                   const float* __restrict__ weight) {
    const size_t NT4 = (size_t)B_ * N_ * DIN_ / 4;            // 524288 float4s
    size_t i = (size_t)blockIdx.x * 256 + threadIdx.x;        // total 589824
    float4 v;
    __nv_bfloat16 *hB, *lB;
    size_t off;
    if (i < NT4) {
        v = reinterpret_cast<const float4*>(text)[i];
        hB = g_text_hi; lB = g_text_lo; off = i * 4;
    } else {
        size_t j = i - NT4;
        v = reinterpret_cast<const float4*>(weight)[j];
        hB = g_W_hi; lB = g_W_lo; off = j * 4;
    }
    uint32_t h0, l0, h1, l1;
    split_pack2(v.x, v.y, h0, l0);
    split_pack2(v.z, v.w, h1, l1);
    *reinterpret_cast<uint2*>(hB + off) = make_uint2(h0, h1);
    *reinterpret_cast<uint2*>(lB + off) = make_uint2(l0, l1);
}

// ---------------------------------------------------------------------------
// rowsum: one warp per adjacency row -> g_rinv.
// ---------------------------------------------------------------------------
__global__ void rowsum_kernel(const float* __restrict__ adj) {
    int row  = blockIdx.x * blockDim.y + threadIdx.y;
    int lane = threadIdx.x;
    const float* p = adj + (size_t)row * N_;
    float s = 0.f;
#pragma unroll
    for (int t = 0; t < N_ / 128; ++t) {
        float4 v = *reinterpret_cast<const float4*>(p + t * 128 + lane * 4);
        s += (v.x + v.y) + (v.z + v.w);
    }
#pragma unroll
    for (int o = 16; o > 0; o >>= 1) s += __shfl_xor_sync(0xffffffffu, s, o);
    if (lane == 0) g_rinv[row] = (s == 0.f) ? 0.f : 1.0f / s;
}

// ---------------------------------------------------------------------------
// Stage 1: Z[b,r] = text[b] @ W[r]  (HMMA split-bf16); writes Z hi/lo bf16.
// ---------------------------------------------------------------------------
__global__ __launch_bounds__(256, 1) void rgc_stage1() {
    extern __shared__ char smem[];
    const uint32_t sb = smem_u32(smem);
    const int tid = threadIdx.x, lane = tid & 31, warp = tid >> 5;
    const int wm = warp & 3, wn = warp >> 2;
    const int g = lane >> 3, lr = lane & 7;

    const int bz = blockIdx.z;            // b*R + r
    const int b  = bz >> 2, r = bz & 3;
    const int tile_m = blockIdx.y * 128;  // j
    const int tile_n = blockIdx.x * 128;  // d

    float acc[2][8][4];
#pragma unroll
    for (int mf = 0; mf < 2; ++mf)
#pragma unroll
        for (int nf = 0; nf < 8; ++nf)
#pragma unroll
            for (int q = 0; q < 4; ++q) acc[mf][nf][q] = 0.f;

    // loads for chunk kc into buffer bufb
    auto issue = [&](int kc, uint32_t bufb) {
        // A = text split: 128 rows x 64 k
        const __nv_bfloat16* th = g_text_hi + ((size_t)b * N_ + tile_m) * DIN_ + kc * 64;
        const __nv_bfloat16* tl = g_text_lo + ((size_t)b * N_ + tile_m) * DIN_ + kc * 64;
#pragma unroll
        for (int i = 0; i < 4; ++i) {
            int idx = i * 256 + tid;
            int row = idx >> 3, k8 = idx & 7;
            uint32_t d = bufb + row * A_STRIDE + k8 * 16;
            CP_ASYNC16(sb + d + OFF_AHI, th + (size_t)row * DIN_ + k8 * 8);
            CP_ASYNC16(sb + d + OFF_ALO, tl + (size_t)row * DIN_ + k8 * 8);
        }
        // B = W split: 64 k x 128 d
        const __nv_bfloat16* wh = g_W_hi + ((size_t)r * DIN_ + kc * 64) * DOUT_ + tile_n;
        const __nv_bfloat16* wl = g_W_lo + ((size_t)r * DIN_ + kc * 64) * DOUT_ + tile_n;
#pragma unroll
        for (int i = 0; i < 4; ++i) {
            int idx = i * 256 + tid;
            int k = idx >> 4, n16 = idx & 15;
            uint32_t d = bufb + k * B_STRIDE + n16 * 16;
            CP_ASYNC16(sb + d + OFF_BHI, wh + (size_t)k * DOUT_ + n16 * 8);
            CP_ASYNC16(sb + d + OFF_BLO, wl + (size_t)k * DOUT_ + n16 * 8);
        }
        CP_COMMIT();
    };

    issue(0, 0);
    CP_WAIT0();
    __syncthreads();

    for (int c = 0; c < 4; ++c) {
        uint32_t bufb = (c & 1) * BUF_BYTES;
        if (c + 1 < 4) issue(c + 1, ((c + 1) & 1) * BUF_BYTES);
        compute_chunk(sb + bufb, wm, wn, g, lr, acc);
        CP_WAIT0();
        __syncthreads();
    }

    // Epilogue: split Z -> g_Z hi/lo
#pragma unroll
    for (int mf = 0; mf < 2; ++mf)
#pragma unroll
        for (int nf = 0; nf < 8; ++nf) {
            int row0 = tile_m + wm * 32 + mf * 16 + (lane >> 2);
            int col  = tile_n + wn * 64 + nf * 8 + (lane & 3) * 2;
            uint32_t hw, lw;
            size_t off0 = ((size_t)bz * N_ + row0) * DOUT_ + col;
            split_pack2(acc[mf][nf][0], acc[mf][nf][1], hw, lw);
            *reinterpret_cast<uint32_t*>(&g_Z_hi[off0]) = hw;
            *reinterpret_cast<uint32_t*>(&g_Z_lo[off0]) = lw;
            size_t off1 = off0 + (size_t)8 * DOUT_;
            split_pack2(acc[mf][nf][2], acc[mf][nf][3], hw, lw);
            *reinterpret_cast<uint32_t*>(&g_Z_hi[off1]) = hw;
            *reinterpret_cast<uint32_t*>(&g_Z_lo[off1]) = lw;
        }
}

// ---------------------------------------------------------------------------
// Stage 2: out[b] = bias + sum_r diag(rinv) adj[b,r] @ Z[b,r]   (HMMA split-bf16)
// rinv folded into adj->bf16 conversion; single accumulator across r.
// ---------------------------------------------------------------------------
__global__ __launch_bounds__(256, 1) void rgc_stage2(const float* __restrict__ adj,
                                                     const float* __restrict__ bias,
                                                     float* __restrict__ out) {
    extern __shared__ char smem[];
    const uint32_t sb = smem_u32(smem);
    const int tid = threadIdx.x, lane = tid & 31, warp = tid >> 5;
    const int wm = warp & 3, wn = warp >> 2;
    const int g = lane >> 3, lr = lane & 7;

    const int b      = blockIdx.z;
    const int tile_m = blockIdx.y * 128;  // i
    const int tile_n = blockIdx.x * 128;  // d

    float acc[2][8][4];
#pragma unroll
    for (int mf = 0; mf < 2; ++mf)
#pragma unroll
        for (int nf = 0; nf < 8; ++nf)
#pragma unroll
            for (int q = 0; q < 4; ++q) acc[mf][nf][q] = 0.f;

    float4 st[8];
    float  rvs[8];

    // issue loads for chunk c: cp.async B (Z split) + LDG adj into regs
    auto issue = [&](int c) {
        const int r = c >> 4, kc = c & 15;
        const uint32_t bufb = (uint32_t)(c & 1) * BUF_BYTES;
        const __nv_bfloat16* zh = g_Z_hi + (((size_t)(b * R_ + r)) * N_ + kc * 64) * DOUT_ + tile_n;
        const __nv_bfloat16* zl = g_Z_lo + (((size_t)(b * R_ + r)) * N_ + kc * 64) * DOUT_ + tile_n;
#pragma unroll
        for (int i = 0; i < 4; ++i) {
            int idx = i * 256 + tid;
            int k = idx >> 4, n16 = idx & 15;
            uint32_t d = bufb + k * B_STRIDE + n16 * 16;
            CP_ASYNC16(sb + d + OFF_BHI, zh + (size_t)k * DOUT_ + n16 * 8);
            CP_ASYNC16(sb + d + OFF_BLO, zl + (size_t)k * DOUT_ + n16 * 8);
        }
        CP_COMMIT();
        const float* ap = adj + (((size_t)(b * R_ + r)) * N_ + tile_m) * N_ + kc * 64;
        const float* rp = g_rinv + (b * R_ + r) * N_ + tile_m;
#pragma unroll
        for (int i = 0; i < 8; ++i) {
            int row = i * 16 + (tid >> 4);
            int c4  = tid & 15;
            st[i]  = *reinterpret_cast<const float4*>(ap + (size_t)row * N_ + c4 * 4);
            rvs[i] = rp[row];
        }
    };
    // convert staged adj regs -> smem (with rinv scaling)
    auto store_adj = [&](int c) {
        const uint32_t bufb = (uint32_t)(c & 1) * BUF_BYTES;
#pragma unroll
        for (int i = 0; i < 8; ++i) {
            int row = i * 16 + (tid >> 4);
            int c4  = tid & 15;
            float rv = rvs[i];
            uint32_t h0, l0, h1, l1;
            split_pack2(st[i].x * rv, st[i].y * rv, h0, l0);
            split_pack2(st[i].z * rv, st[i].w * rv, h1, l1);
            char* base = smem + bufb + row * A_STRIDE + c4 * 8;
            *reinterpret_cast<uint2*>(base + OFF_AHI) = make_uint2(h0, h1);
            *reinterpret_cast<uint2*>(base + OFF_ALO) = make_uint2(l0, l1);
        }
    };

    issue(0);
    store_adj(0);
    CP_WAIT0();
    __syncthreads();

    for (int c = 0; c < 64; ++c) {
        const uint32_t bufb = (uint32_t)(c & 1) * BUF_BYTES;
        if (c + 1 < 64) issue(c + 1);
        compute_chunk(sb + bufb, wm, wn, g, lr, acc);
        if (c + 1 < 64) store_adj(c + 1);
        CP_WAIT0();
        __syncthreads();
    }

    // Epilogue: + bias, store fp32
#pragma unroll
    for (int mf = 0; mf < 2; ++mf)
#pragma unroll
        for (int nf = 0; nf < 8; ++nf) {
            int row0 = tile_m + wm * 32 + mf * 16 + (lane >> 2);
            int col  = tile_n + wn * 64 + nf * 8 + (lane & 3) * 2;
            float b0 = bias[col], b1 = bias[col + 1];
            float* o0 = out + ((size_t)b * N_ + row0) * DOUT_ + col;
            *reinterpret_cast<float2*>(o0) =
                make_float2(acc[mf][nf][0] + b0, acc[mf][nf][1] + b1);
            float* o1 = o0 + (size_t)8 * DOUT_;
            *reinterpret_cast<float2*>(o1) =
                make_float2(acc[mf][nf][2] + b0, acc[mf][nf][3] + b1);
        }
}

// ---------------------------------------------------------------------------
extern "C" void kernel_launch(void* const* d_in, const int* in_sizes, int n_in,
                              void* d_out, int out_size) {
    const float* text   = (const float*)d_in[0];  // [8,1024,256]
    const float* adj    = (const float*)d_in[1];  // [8,4,1024,1024]
    const float* weight = (const float*)d_in[2];  // [4,256,256]
    const float* bias   = (const float*)d_in[3];  // [256]
    float* out = (float*)d_out;                   // [8,1024,256]

    cudaFuncSetAttribute(rgc_stage1, cudaFuncAttributeMaxDynamicSharedMemorySize, SMEM_TOTAL);
    cudaFuncSetAttribute(rgc_stage2, cudaFuncAttributeMaxDynamicSharedMemorySize, SMEM_TOTAL);

    // 1) split text & W to bf16 hi/lo
    conv_inputs<<<2304, 256>>>(text, weight);
    // 2) rinv = 1/rowsum(adj)
    rowsum_kernel<<<(B_ * R_ * N_) / 8, dim3(32, 8)>>>(adj);
    // 3) Z = text @ W (split bf16 HMMA)
    rgc_stage1<<<dim3(DOUT_ / 128, N_ / 128, B_ * R_), 256, SMEM_TOTAL>>>();
    // 4) out = bias + sum_r diag(rinv) adj @ Z (split bf16 HMMA)
    rgc_stage2<<<dim3(DOUT_ / 128, N_ / 128, B_), 256, SMEM_TOTAL>>>(adj, bias, out);
}

// round 7
// speedup vs baseline: 4.2522x; 1.3039x over previous
#include <cuda_runtime.h>
#include <cuda_fp16.h>
#include <cstdint>

#define B_    8
#define R_    4
#define N_    1024
#define DIN_  256
#define DOUT_ 256

#define ADJ_SCALE 1024.0f
#define INV_SCALE (1.0f / 1024.0f)

// ---------------------------------------------------------------------------
// Global scratch (device globals; allocation in kernel_launch is forbidden)
// ---------------------------------------------------------------------------
__device__ __half g_text_hi[(size_t)B_ * N_ * DIN_];
__device__ __half g_text_lo[(size_t)B_ * N_ * DIN_];
__device__ __half g_W[(size_t)R_ * DIN_ * DOUT_];
__device__ __half g_Z[(size_t)B_ * R_ * N_ * DOUT_];               // Z[b,r][j][d] fp16
__device__ __half g_adj_hi[(size_t)B_ * R_ * N_ * N_];             // rinv*1024-scaled adj
__device__ __half g_adj_lo[(size_t)B_ * R_ * N_ * N_];

// ---------------------------------------------------------------------------
// PTX helpers (compute_103-safe: mma.sync / ldmatrix / cp.async)
// ---------------------------------------------------------------------------
__device__ __forceinline__ uint32_t smem_u32(const void* p) {
    uint32_t a;
    asm("{ .reg .u64 t; cvta.to.shared.u64 t, %1; cvt.u32.u64 %0, t; }" : "=r"(a) : "l"(p));
    return a;
}
__device__ __forceinline__ void ldsm_x4(uint32_t addr, uint32_t& r0, uint32_t& r1,
                                        uint32_t& r2, uint32_t& r3) {
    asm volatile("ldmatrix.sync.aligned.m8n8.x4.shared.b16 {%0,%1,%2,%3}, [%4];"
                 : "=r"(r0), "=r"(r1), "=r"(r2), "=r"(r3) : "r"(addr));
}
__device__ __forceinline__ void ldsm_x4_t(uint32_t addr, uint32_t& r0, uint32_t& r1,
                                          uint32_t& r2, uint32_t& r3) {
    asm volatile("ldmatrix.sync.aligned.m8n8.x4.trans.shared.b16 {%0,%1,%2,%3}, [%4];"
                 : "=r"(r0), "=r"(r1), "=r"(r2), "=r"(r3) : "r"(addr));
}
__device__ __forceinline__ void mma_f16(float* c, const uint32_t a[4], uint32_t b0, uint32_t b1) {
    asm volatile("mma.sync.aligned.m16n8k16.row.col.f32.f16.f16.f32 "
                 "{%0,%1,%2,%3}, {%4,%5,%6,%7}, {%8,%9}, {%0,%1,%2,%3};"
                 : "+f"(c[0]), "+f"(c[1]), "+f"(c[2]), "+f"(c[3])
                 : "r"(a[0]), "r"(a[1]), "r"(a[2]), "r"(a[3]), "r"(b0), "r"(b1));
}
#define CP_ASYNC16(dst, src) \
    asm volatile("cp.async.cg.shared.global [%0], [%1], 16;" :: "r"(dst), "l"(src) : "memory")
#define CP_COMMIT()  asm volatile("cp.async.commit_group;" ::: "memory")
#define CP_WAIT0()   asm volatile("cp.async.wait_group 0;" ::: "memory")
#define CP_WAIT2()   asm volatile("cp.async.wait_group 2;" ::: "memory")

__device__ __forceinline__ void split_h2(float x, float y, uint32_t& hw, uint32_t& lw) {
    __half hx = __float2half_rn(x), hy = __float2half_rn(y);
    hw = ((uint32_t)__half_as_ushort(hy) << 16) | __half_as_ushort(hx);
    __half lx = __float2half_rn(x - __half2float(hx));
    __half ly = __float2half_rn(y - __half2float(hy));
    lw = ((uint32_t)__half_as_ushort(ly) << 16) | __half_as_ushort(lx);
}
__device__ __forceinline__ uint32_t pack_h2(float x, float y) {
    __half hx = __float2half_rn(x), hy = __float2half_rn(y);
    return ((uint32_t)__half_as_ushort(hy) << 16) | __half_as_ushort(hx);
}

// ---------------------------------------------------------------------------
// smem layout (per pipeline buffer), padded strides — conflict-free ldmatrix
//   A: 128 rows x 64 fp16 (128B) stride 144  -> 18432 B per array (hi, lo)
//   B:  64 rows x 128 fp16 (256B) stride 272 -> 17408 B
// ---------------------------------------------------------------------------
#define A_STRIDE  144
#define B_STRIDE  272
#define OFF_AHI   0
#define OFF_ALO   18432
#define OFF_B     36864
#define BUF_BYTES 54272
#define SMEM1_TOTAL (2 * BUF_BYTES)    // stage 1: double buffer
#define SMEM2_TOTAL (4 * BUF_BYTES)    // stage 2: quad buffer (217088 B)

// Warp (wm,wn) computes 32x64 of the 128x128 CTA tile. 2 passes: a_hi*b + a_lo*b.
__device__ __forceinline__ void compute_chunk(uint32_t sb_buf, int wm, int wn, int g, int lr,
                                              float (&acc)[2][8][4]) {
#pragma unroll
    for (int ks = 0; ks < 4; ++ks) {
        const int k0 = ks * 16;
        uint32_t ah[2][4], al[2][4];
#pragma unroll
        for (int mf = 0; mf < 2; ++mf) {
            uint32_t row  = wm * 32 + mf * 16 + (g & 1) * 8 + lr;
            uint32_t colb = (uint32_t)((g >> 1) * 16 + k0 * 2);
            ldsm_x4(sb_buf + OFF_AHI + row * A_STRIDE + colb,
                    ah[mf][0], ah[mf][1], ah[mf][2], ah[mf][3]);
            ldsm_x4(sb_buf + OFF_ALO + row * A_STRIDE + colb,
                    al[mf][0], al[mf][1], al[mf][2], al[mf][3]);
        }
        uint32_t bb[8][2];
#pragma unroll
        for (int nb = 0; nb < 4; ++nb) {
            uint32_t krow = (uint32_t)(k0 + (g & 1) * 8 + lr);
            uint32_t colb = (uint32_t)((wn * 64 + nb * 16 + (g >> 1) * 8) * 2);
            uint32_t q0, q1, q2, q3;
            ldsm_x4_t(sb_buf + OFF_B + krow * B_STRIDE + colb, q0, q1, q2, q3);
            bb[nb * 2][0] = q0; bb[nb * 2][1] = q1;
            bb[nb * 2 + 1][0] = q2; bb[nb * 2 + 1][1] = q3;
        }
#pragma unroll
        for (int mf = 0; mf < 2; ++mf)
#pragma unroll
            for (int nf = 0; nf < 8; ++nf) {
                mma_f16(acc[mf][nf], ah[mf], bb[nf][0], bb[nf][1]);
                mma_f16(acc[mf][nf], al[mf], bb[nf][0], bb[nf][1]);
            }
    }
}

// ---------------------------------------------------------------------------
// conv_inputs: text -> fp16 hi/lo ; W -> fp16 single.
// ---------------------------------------------------------------------------
__global__ __launch_bounds__(256) void conv_inputs(const float* __restrict__ text,
                                                   const float* __restrict__ weight) {
    const size_t NT4 = (size_t)B_ * N_ * DIN_ / 4;            // 524288 float4s
    size_t i = (size_t)blockIdx.x * 256 + threadIdx.x;        // total 589824
    if (i < NT4) {
        float4 v = reinterpret_cast<const float4*>(text)[i];
        uint32_t h0, l0, h1, l1;
        split_h2(v.x, v.y, h0, l0);
        split_h2(v.z, v.w, h1, l1);
        *reinterpret_cast<uint2*>(g_text_hi + i * 4) = make_uint2(h0, h1);
        *reinterpret_cast<uint2*>(g_text_lo + i * 4) = make_uint2(l0, l1);
    } else {
        size_t j = i - NT4;
        float4 v = reinterpret_cast<const float4*>(weight)[j];
        *reinterpret_cast<uint2*>(g_W + j * 4) =
            make_uint2(pack_h2(v.x, v.y), pack_h2(v.z, v.w));
    }
}

// ---------------------------------------------------------------------------
// adj_convert: one warp per row. rowsum -> rinv; write (adj * rinv * 1024) as
// fp16 hi/lo. Reads adj once, fuses old rowsum kernel.
// ---------------------------------------------------------------------------
__global__ __launch_bounds__(256) void adj_convert(const float* __restrict__ adj) {
    const int warp = threadIdx.x >> 5, lane = threadIdx.x & 31;
    const int row  = blockIdx.x * 8 + warp;                    // 0 .. 32767
    const float* p = adj + (size_t)row * N_;

    float4 v[8];
    float s = 0.f;
#pragma unroll
    for (int t = 0; t < 8; ++t) {
        v[t] = *reinterpret_cast<const float4*>(p + t * 128 + lane * 4);
        s += (v[t].x + v[t].y) + (v[t].z + v[t].w);
    }
#pragma unroll
    for (int o = 16; o > 0; o >>= 1) s += __shfl_xor_sync(0xffffffffu, s, o);
    const float rinv = (s == 0.f) ? 0.f : ADJ_SCALE / s;

    __half* hp = g_adj_hi + (size_t)row * N_;
    __half* lp = g_adj_lo + (size_t)row * N_;
#pragma unroll
    for (int t = 0; t < 8; ++t) {
        uint32_t h0, l0, h1, l1;
        split_h2(v[t].x * rinv, v[t].y * rinv, h0, l0);
        split_h2(v[t].z * rinv, v[t].w * rinv, h1, l1);
        *reinterpret_cast<uint2*>(hp + t * 128 + lane * 4) = make_uint2(h0, h1);
        *reinterpret_cast<uint2*>(lp + t * 128 + lane * 4) = make_uint2(l0, l1);
    }
}

// ---------------------------------------------------------------------------
// Stage 1: Z[b,r] = text[b] @ W[r]  (fp16 2-pass HMMA); writes Z fp16.
// ---------------------------------------------------------------------------
__global__ __launch_bounds__(256, 1) void rgc_stage1() {
    extern __shared__ char smem[];
    const uint32_t sb = smem_u32(smem);
    const int tid = threadIdx.x, lane = tid & 31, warp = tid >> 5;
    const int wm = warp & 3, wn = warp >> 2;
    const int g = lane >> 3, lr = lane & 7;

    const int bz = blockIdx.z;            // b*R + r
    const int b  = bz >> 2, r = bz & 3;
    const int tile_m = blockIdx.y * 128;  // j
    const int tile_n = blockIdx.x * 128;  // d

    float acc[2][8][4];
#pragma unroll
    for (int mf = 0; mf < 2; ++mf)
#pragma unroll
        for (int nf = 0; nf < 8; ++nf)
#pragma unroll
            for (int q = 0; q < 4; ++q) acc[mf][nf][q] = 0.f;

    auto issue = [&](int kc) {
        const uint32_t bufb = (uint32_t)(kc & 1) * BUF_BYTES;
        const __half* th = g_text_hi + ((size_t)b * N_ + tile_m) * DIN_ + kc * 64;
        const __half* tl = g_text_lo + ((size_t)b * N_ + tile_m) * DIN_ + kc * 64;
#pragma unroll
        for (int i = 0; i < 4; ++i) {
            int idx = i * 256 + tid;
            int row = idx >> 3, k8 = idx & 7;
            uint32_t d = bufb + row * A_STRIDE + k8 * 16;
            CP_ASYNC16(sb + d + OFF_AHI, th + (size_t)row * DIN_ + k8 * 8);
            CP_ASYNC16(sb + d + OFF_ALO, tl + (size_t)row * DIN_ + k8 * 8);
        }
        const __half* wp = g_W + ((size_t)r * DIN_ + kc * 64) * DOUT_ + tile_n;
#pragma unroll
        for (int i = 0; i < 4; ++i) {
            int idx = i * 256 + tid;
            int k = idx >> 4, n16 = idx & 15;
            CP_ASYNC16(sb + bufb + k * B_STRIDE + n16 * 16 + OFF_B,
                       wp + (size_t)k * DOUT_ + n16 * 8);
        }
        CP_COMMIT();
    };

    issue(0);
    CP_WAIT0();
    __syncthreads();

    for (int c = 0; c < 4; ++c) {
        if (c + 1 < 4) issue(c + 1);
        compute_chunk(sb + (uint32_t)(c & 1) * BUF_BYTES, wm, wn, g, lr, acc);
        CP_WAIT0();
        __syncthreads();
    }

    // Epilogue: Z (single fp16)
#pragma unroll
    for (int mf = 0; mf < 2; ++mf)
#pragma unroll
        for (int nf = 0; nf < 8; ++nf) {
            int row0 = tile_m + wm * 32 + mf * 16 + (lane >> 2);
            int col  = tile_n + wn * 64 + nf * 8 + (lane & 3) * 2;
            size_t off0 = ((size_t)bz * N_ + row0) * DOUT_ + col;
            *reinterpret_cast<uint32_t*>(&g_Z[off0]) = pack_h2(acc[mf][nf][0], acc[mf][nf][1]);
            size_t off1 = off0 + (size_t)8 * DOUT_;
            *reinterpret_cast<uint32_t*>(&g_Z[off1]) = pack_h2(acc[mf][nf][2], acc[mf][nf][3]);
        }
}

// ---------------------------------------------------------------------------
// Stage 2: out[b] = bias + (1/1024) * sum_r adjn16[b,r] @ Z[b,r]
// Pure cp.async -> ldmatrix -> HMMA pipeline, 4-stage buffering.
// ---------------------------------------------------------------------------
__global__ __launch_bounds__(256, 1) void rgc_stage2(const float* __restrict__ bias,
                                                     float* __restrict__ out) {
    extern __shared__ char smem[];
    const uint32_t sb = smem_u32(smem);
    const int tid = threadIdx.x, lane = tid & 31, warp = tid >> 5;
    const int wm = warp & 3, wn = warp >> 2;
    const int g = lane >> 3, lr = lane & 7;

    const int b      = blockIdx.z;
    const int tile_m = blockIdx.y * 128;  // i
    const int tile_n = blockIdx.x * 128;  // d

    float acc[2][8][4];
#pragma unroll
    for (int mf = 0; mf < 2; ++mf)
#pragma unroll
        for (int nf = 0; nf < 8; ++nf)
#pragma unroll
            for (int q = 0; q < 4; ++q) acc[mf][nf][q] = 0.f;

    // chunk c: r = c>>4, kc = c&15 (K=64 slices of each relation's 1024-wide K)
    auto issue = [&](int c) {
        const int r = c >> 4, kc = c & 15;
        const uint32_t bufb = (uint32_t)(c & 3) * BUF_BYTES;
        const __half* ah = g_adj_hi + (((size_t)(b * R_ + r)) * N_ + tile_m) * N_ + kc * 64;
        const __half* al = g_adj_lo + (((size_t)(b * R_ + r)) * N_ + tile_m) * N_ + kc * 64;
#pragma unroll
        for (int i = 0; i < 4; ++i) {
            int idx = i * 256 + tid;
            int row = idx >> 3, k8 = idx & 7;
            uint32_t d = bufb + row * A_STRIDE + k8 * 16;
            CP_ASYNC16(sb + d + OFF_AHI, ah + (size_t)row * N_ + k8 * 8);
            CP_ASYNC16(sb + d + OFF_ALO, al + (size_t)row * N_ + k8 * 8);
        }
        const __half* zp = g_Z + (((size_t)(b * R_ + r)) * N_ + kc * 64) * DOUT_ + tile_n;
#pragma unroll
        for (int i = 0; i < 4; ++i) {
            int idx = i * 256 + tid;
            int k = idx >> 4, n16 = idx & 15;
            CP_ASYNC16(sb + bufb + k * B_STRIDE + n16 * 16 + OFF_B,
                       zp + (size_t)k * DOUT_ + n16 * 8);
        }
        CP_COMMIT();
    };

    issue(0); issue(1); issue(2);

    for (int c = 0; c < 64; ++c) {
        CP_WAIT2();                      // chunk c arrived (2 younger may be in flight)
        __syncthreads();
        compute_chunk(sb + (uint32_t)(c & 3) * BUF_BYTES, wm, wn, g, lr, acc);
        __syncthreads();                 // all warps done with buffer (c) before reuse
        if (c + 3 < 64) issue(c + 3); else CP_COMMIT();   // keep group count uniform
    }

    // Epilogue: undo ADJ_SCALE, add bias, store fp32
#pragma unroll
    for (int mf = 0; mf < 2; ++mf)
#pragma unroll
        for (int nf = 0; nf < 8; ++nf) {
            int row0 = tile_m + wm * 32 + mf * 16 + (lane >> 2);
            int col  = tile_n + wn * 64 + nf * 8 + (lane & 3) * 2;
            float b0 = bias[col], b1 = bias[col + 1];
            float* o0 = out + ((size_t)b * N_ + row0) * DOUT_ + col;
            *reinterpret_cast<float2*>(o0) =
                make_float2(acc[mf][nf][0] * INV_SCALE + b0, acc[mf][nf][1] * INV_SCALE + b1);
            float* o1 = o0 + (size_t)8 * DOUT_;
            *reinterpret_cast<float2*>(o1) =
                make_float2(acc[mf][nf][2] * INV_SCALE + b0, acc[mf][nf][3] * INV_SCALE + b1);
        }
}

// ---------------------------------------------------------------------------
extern "C" void kernel_launch(void* const* d_in, const int* in_sizes, int n_in,
                              void* d_out, int out_size) {
    const float* text   = (const float*)d_in[0];  // [8,1024,256]
    const float* adj    = (const float*)d_in[1];  // [8,4,1024,1024]
    const float* weight = (const float*)d_in[2];  // [4,256,256]
    const float* bias   = (const float*)d_in[3];  // [256]
    float* out = (float*)d_out;                   // [8,1024,256]

    cudaFuncSetAttribute(rgc_stage1, cudaFuncAttributeMaxDynamicSharedMemorySize, SMEM1_TOTAL);
    cudaFuncSetAttribute(rgc_stage2, cudaFuncAttributeMaxDynamicSharedMemorySize, SMEM2_TOTAL);

    // 1) text -> fp16 hi/lo, W -> fp16
    conv_inputs<<<2304, 256>>>(text, weight);
    // 2) adj -> fp16 hi/lo, row-normalized (rowsum fused), x1024 range scale
    adj_convert<<<(B_ * R_ * N_) / 8, 256>>>(adj);
    // 3) Z = text @ W (fp16 2-pass HMMA)
    rgc_stage1<<<dim3(DOUT_ / 128, N_ / 128, B_ * R_), 256, SMEM1_TOTAL>>>();
    // 4) out = bias + (1/1024) * sum_r adjn @ Z (fp16 2-pass HMMA)
    rgc_stage2<<<dim3(DOUT_ / 128, N_ / 128, B_), 256, SMEM2_TOTAL>>>(bias, out);
}